// round 1
// baseline (speedup 1.0000x reference)
#include <cuda_runtime.h>

// SpikeLoss: loss = 0.5 * sum( (outputs - psp(target))^2 )
// psp: syn_t = syn_{t-1}*(1-1/tau) + x_t ; y_t = syn_t/tau ; tau = 5.0
// Shapes: [B=32, C=256, H=4, W=4, T=100] -> 131072 rows x 100 timesteps.
// One thread per row; scan carried in registers; deterministic 2-stage reduce.

#define T_STEPS 100
#define VEC (T_STEPS / 4)          // 25 float4 per row
#define BLOCK 256
#define MAX_BLOCKS 4096

__device__ float g_partials[MAX_BLOCKS];

__global__ void __launch_bounds__(BLOCK)
spike_loss_rows(const float* __restrict__ outputs,
                const float* __restrict__ target,
                int rows)
{
    const int row = blockIdx.x * BLOCK + threadIdx.x;
    float acc = 0.0f;

    if (row < rows) {
        const float4* __restrict__ o4 =
            reinterpret_cast<const float4*>(outputs + (size_t)row * T_STEPS);
        const float4* __restrict__ x4 =
            reinterpret_cast<const float4*>(target  + (size_t)row * T_STEPS);

        const float decay   = 0.8f;   // 1 - 1/tau
        const float inv_tau = 0.2f;   // 1/tau
        float syn = 0.0f;

        #pragma unroll 5
        for (int i = 0; i < VEC; ++i) {
            float4 x = __ldg(&x4[i]);
            float4 o = __ldg(&o4[i]);

            float d;
            syn = fmaf(syn, decay, x.x); d = fmaf(-syn, inv_tau, o.x); acc = fmaf(d, d, acc);
            syn = fmaf(syn, decay, x.y); d = fmaf(-syn, inv_tau, o.y); acc = fmaf(d, d, acc);
            syn = fmaf(syn, decay, x.z); d = fmaf(-syn, inv_tau, o.z); acc = fmaf(d, d, acc);
            syn = fmaf(syn, decay, x.w); d = fmaf(-syn, inv_tau, o.w); acc = fmaf(d, d, acc);
        }
    }

    // Block reduction (deterministic within a block: fixed tree order).
    __shared__ float warp_sums[BLOCK / 32];
    const int lane = threadIdx.x & 31;
    const int wid  = threadIdx.x >> 5;

    #pragma unroll
    for (int off = 16; off > 0; off >>= 1)
        acc += __shfl_down_sync(0xFFFFFFFFu, acc, off);
    if (lane == 0) warp_sums[wid] = acc;
    __syncthreads();

    if (wid == 0) {
        float v = (lane < BLOCK / 32) ? warp_sums[lane] : 0.0f;
        #pragma unroll
        for (int off = 16; off > 0; off >>= 1)
            v += __shfl_down_sync(0xFFFFFFFFu, v, off);
        if (lane == 0) g_partials[blockIdx.x] = v;
    }
}

__global__ void __launch_bounds__(1024)
spike_loss_finalize(float* __restrict__ out, int nblocks)
{
    __shared__ float warp_sums[32];
    float v = 0.0f;
    // Fixed iteration order -> deterministic.
    for (int i = threadIdx.x; i < nblocks; i += 1024)
        v += g_partials[i];

    const int lane = threadIdx.x & 31;
    const int wid  = threadIdx.x >> 5;
    #pragma unroll
    for (int off = 16; off > 0; off >>= 1)
        v += __shfl_down_sync(0xFFFFFFFFu, v, off);
    if (lane == 0) warp_sums[wid] = v;
    __syncthreads();

    if (wid == 0) {
        float s = (lane < 32) ? warp_sums[lane] : 0.0f;
        #pragma unroll
        for (int off = 16; off > 0; off >>= 1)
            s += __shfl_down_sync(0xFFFFFFFFu, s, off);
        if (lane == 0) *out = 0.5f * s;
    }
}

extern "C" void kernel_launch(void* const* d_in, const int* in_sizes, int n_in,
                              void* d_out, int out_size)
{
    const float* outputs = (const float*)d_in[0];
    const float* target  = (const float*)d_in[1];
    float* out = (float*)d_out;

    const int n    = in_sizes[0];
    const int rows = n / T_STEPS;
    const int blocks = (rows + BLOCK - 1) / BLOCK;   // 512 for the given shape

    spike_loss_rows<<<blocks, BLOCK>>>(outputs, target, rows);
    spike_loss_finalize<<<1, 1024>>>(out, blocks);
}